// round 1
// baseline (speedup 1.0000x reference)
#include <cuda_runtime.h>
#include <math.h>

#define LSEQ     2048
#define HIDDEN   2048
#define INTER    4096
#define HEADS    64
#define HEAD_DIM 64
#define STATE    64
#define KCONV    4
#define CONV_DIM (INTER + 2 * STATE)            // 4224
#define PROJ     (INTER + CONV_DIM + HEADS)     // 8384

// ---------------- scratch (device globals; no allocation in kernel_launch) ----
__device__ float g_proj[(size_t)LSEQ * PROJ];        // 68.7 MB
__device__ float g_conv[(size_t)LSEQ * CONV_DIM];    // 34.6 MB
__device__ float g_y[(size_t)LSEQ * INTER];          // 33.5 MB
__device__ float g_dtv[LSEQ * HEADS];
__device__ float g_dA[LSEQ * HEADS];

// ---------------- GEMM: C[M,N] = A[M,K] * B[N,K]^T (both row-major, K contiguous)
__global__ __launch_bounds__(256) void gemm_abt(const float* __restrict__ A,
                                                const float* __restrict__ Bm,
                                                float* __restrict__ C,
                                                int M, int N, int K)
{
    constexpr int BM = 128, BN = 128, BK = 16;
    __shared__ float As[BK][BM];
    __shared__ float Bs[BK][BN];
    const int tid = threadIdx.x;
    const int m0 = blockIdx.y * BM;
    const int n0 = blockIdx.x * BN;
    const int tx = tid & 15;
    const int ty = tid >> 4;

    float acc[8][8];
#pragma unroll
    for (int i = 0; i < 8; ++i)
#pragma unroll
        for (int j = 0; j < 8; ++j) acc[i][j] = 0.f;

    for (int k0 = 0; k0 < K; k0 += BK) {
#pragma unroll
        for (int it = 0; it < 2; ++it) {
            int id  = tid + it * 256;   // 0..511
            int row = id >> 2;
            int kq  = id & 3;
            {
                int gm = m0 + row;
                float4 v = make_float4(0.f, 0.f, 0.f, 0.f);
                if (gm < M)
                    v = *reinterpret_cast<const float4*>(&A[(size_t)gm * K + k0 + kq * 4]);
                As[kq * 4 + 0][row] = v.x;
                As[kq * 4 + 1][row] = v.y;
                As[kq * 4 + 2][row] = v.z;
                As[kq * 4 + 3][row] = v.w;
            }
            {
                int gn = n0 + row;
                float4 v = make_float4(0.f, 0.f, 0.f, 0.f);
                if (gn < N)
                    v = *reinterpret_cast<const float4*>(&Bm[(size_t)gn * K + k0 + kq * 4]);
                Bs[kq * 4 + 0][row] = v.x;
                Bs[kq * 4 + 1][row] = v.y;
                Bs[kq * 4 + 2][row] = v.z;
                Bs[kq * 4 + 3][row] = v.w;
            }
        }
        __syncthreads();
#pragma unroll
        for (int k = 0; k < BK; ++k) {
            float a[8], b[8];
            *reinterpret_cast<float4*>(&a[0]) = *reinterpret_cast<const float4*>(&As[k][ty * 8 + 0]);
            *reinterpret_cast<float4*>(&a[4]) = *reinterpret_cast<const float4*>(&As[k][ty * 8 + 4]);
            *reinterpret_cast<float4*>(&b[0]) = *reinterpret_cast<const float4*>(&Bs[k][tx * 8 + 0]);
            *reinterpret_cast<float4*>(&b[4]) = *reinterpret_cast<const float4*>(&Bs[k][tx * 8 + 4]);
#pragma unroll
            for (int i = 0; i < 8; ++i)
#pragma unroll
                for (int j = 0; j < 8; ++j)
                    acc[i][j] = fmaf(a[i], b[j], acc[i][j]);
        }
        __syncthreads();
    }

#pragma unroll
    for (int i = 0; i < 8; ++i) {
        int gm = m0 + ty * 8 + i;
        if (gm >= M) continue;
#pragma unroll
        for (int j = 0; j < 8; ++j) {
            int gn = n0 + tx * 8 + j;
            if (gn < N) C[(size_t)gm * N + gn] = acc[i][j];
        }
    }
}

// ---------------- causal depthwise conv (K=4) + SiLU over hBC channels --------
__global__ void conv_silu_kernel(const float* __restrict__ conv_w,
                                 const float* __restrict__ conv_b)
{
    int idx = blockIdx.x * blockDim.x + threadIdx.x;
    if (idx >= LSEQ * CONV_DIM) return;
    int c = idx % CONV_DIM;
    int t = idx / CONV_DIM;
    const float4 w = *reinterpret_cast<const float4*>(&conv_w[c * 4]);
    const float* col = g_proj + INTER + c;   // hBC region starts at channel INTER
    float acc = conv_b[c];
    if (t - 3 >= 0) acc = fmaf(col[(size_t)(t - 3) * PROJ], w.x, acc);
    if (t - 2 >= 0) acc = fmaf(col[(size_t)(t - 2) * PROJ], w.y, acc);
    if (t - 1 >= 0) acc = fmaf(col[(size_t)(t - 1) * PROJ], w.z, acc);
    acc = fmaf(col[(size_t)t * PROJ], w.w, acc);
    g_conv[idx] = acc / (1.f + expf(-acc));   // silu
}

// ---------------- dt: softplus(dt + bias), dA = exp(dt * (-exp(A_log))) -------
__global__ void dt_kernel(const float* __restrict__ dt_bias,
                          const float* __restrict__ A_log)
{
    int idx = blockIdx.x * blockDim.x + threadIdx.x;
    if (idx >= LSEQ * HEADS) return;
    int h = idx & (HEADS - 1);
    int t = idx >> 6;
    float z = g_proj[(size_t)t * PROJ + INTER + CONV_DIM + h] + dt_bias[h];
    float d = (z > 20.f) ? z : log1pf(expf(z));
    float A = -expf(A_log[h]);
    g_dtv[idx] = d;
    g_dA[idx]  = expf(d * A);
}

// ---------------- selective scan: grid = 64 heads x 2 p-halves ----------------
__global__ __launch_bounds__(256) void scan_kernel(const float* __restrict__ D)
{
    const int h     = blockIdx.x >> 1;
    const int phalf = blockIdx.x & 1;
    const int tid   = threadIdx.x;
    const int pl    = tid >> 3;            // 0..31  (local p within half)
    const int pg    = phalf * 32 + pl;     // global p 0..63
    const int n0    = (tid & 7) * 8;       // 8 state entries per thread
    const float Dh  = D[h];

    __shared__ float sB[STATE], sC[STATE], sX[32];
    __shared__ float sdt, sdA;

    float s[8];
#pragma unroll
    for (int i = 0; i < 8; ++i) s[i] = 0.f;

    for (int t = 0; t < LSEQ; ++t) {
        const float* row = g_conv + (size_t)t * CONV_DIM;
        if (tid < 64)        sB[tid]        = row[INTER + tid];
        else if (tid < 128)  sC[tid - 64]   = row[INTER + STATE + (tid - 64)];
        else if (tid < 160)  sX[tid - 128]  = row[h * HEAD_DIM + phalf * 32 + (tid - 128)];
        else if (tid == 160) sdt = g_dtv[t * HEADS + h];
        else if (tid == 161) sdA = g_dA[t * HEADS + h];
        __syncthreads();

        const float xv  = sX[pl];
        const float dtx = sdt * xv;
        const float a   = sdA;
        float accv = 0.f;
#pragma unroll
        for (int i = 0; i < 8; ++i) {
            s[i] = fmaf(a, s[i], dtx * sB[n0 + i]);
            accv = fmaf(s[i], sC[n0 + i], accv);
        }
        accv += __shfl_xor_sync(0xffffffffu, accv, 4);
        accv += __shfl_xor_sync(0xffffffffu, accv, 2);
        accv += __shfl_xor_sync(0xffffffffu, accv, 1);
        if ((tid & 7) == 0)
            g_y[(size_t)t * INTER + h * HEAD_DIM + pg] = accv + Dh * xv;
        __syncthreads();
    }
}

// ---------------- RMSNorm (groups=1) * norm_weight * silu(gate), in place -----
__global__ __launch_bounds__(256) void norm_gate_kernel(const float* __restrict__ nw)
{
    const int t = blockIdx.x;
    float* yr = g_y + (size_t)t * INTER;
    __shared__ float red[256];
    float ss = 0.f;
    for (int c = threadIdx.x; c < INTER; c += 256) {
        float v = yr[c];
        ss = fmaf(v, v, ss);
    }
    red[threadIdx.x] = ss;
    __syncthreads();
    for (int off = 128; off > 0; off >>= 1) {
        if (threadIdx.x < off) red[threadIdx.x] += red[threadIdx.x + off];
        __syncthreads();
    }
    const float r = rsqrtf(red[0] / (float)INTER + 1e-6f);
    for (int c = threadIdx.x; c < INTER; c += 256) {
        float g  = g_proj[(size_t)t * PROJ + c];       // gate
        float sg = g / (1.f + expf(-g));               // silu(gate)
        yr[c] = yr[c] * r * nw[c] * sg;
    }
}

// ---------------- launch ------------------------------------------------------
extern "C" void kernel_launch(void* const* d_in, const int* in_sizes, int n_in,
                              void* d_out, int out_size)
{
    const float* hidden     = (const float*)d_in[0];   // [1, 2048, 2048]
    const float* in_proj_w  = (const float*)d_in[1];   // [8384, 2048]
    const float* conv_w     = (const float*)d_in[2];   // [4224, 4]
    const float* conv_b     = (const float*)d_in[3];   // [4224]
    const float* dt_bias    = (const float*)d_in[4];   // [64]
    const float* A_log      = (const float*)d_in[5];   // [64]
    const float* Dv         = (const float*)d_in[6];   // [64]
    const float* norm_w     = (const float*)d_in[7];   // [4096]
    const float* out_proj_w = (const float*)d_in[8];   // [2048, 4096]
    float* out = (float*)d_out;                        // [1, 2048, 2048]

    float *p_proj = nullptr, *p_y = nullptr;
    cudaGetSymbolAddress((void**)&p_proj, g_proj);
    cudaGetSymbolAddress((void**)&p_y, g_y);

    // 1) proj = hidden @ in_proj_w^T   : M=2048, N=8384, K=2048
    {
        dim3 grid((PROJ + 127) / 128, LSEQ / 128);
        gemm_abt<<<grid, 256>>>(hidden, in_proj_w, p_proj, LSEQ, PROJ, HIDDEN);
    }
    // 2) depthwise conv + silu
    {
        int total = LSEQ * CONV_DIM;
        conv_silu_kernel<<<(total + 255) / 256, 256>>>(conv_w, conv_b);
    }
    // 3) dt transform
    {
        int total = LSEQ * HEADS;
        dt_kernel<<<(total + 255) / 256, 256>>>(dt_bias, A_log);
    }
    // 4) selective scan
    scan_kernel<<<HEADS * 2, 256>>>(Dv);
    // 5) rmsnorm * gate
    norm_gate_kernel<<<LSEQ, 256>>>(norm_w);
    // 6) out = y @ out_proj_w^T : M=2048, N=2048, K=4096
    {
        dim3 grid(HIDDEN / 128, LSEQ / 128);
        gemm_abt<<<grid, 256>>>(p_y, out_proj_w, out, LSEQ, HIDDEN, INTER);
    }
}

// round 3
// speedup vs baseline: 3.1088x; 3.1088x over previous
#include <cuda_runtime.h>
#include <cstdint>
#include <math.h>

#define LSEQ     2048
#define HIDDEN   2048
#define INTER    4096
#define HEADS    64
#define HEAD_DIM 64
#define STATE    64
#define KCONV    4
#define CONV_DIM (INTER + 2 * STATE)            // 4224
#define PROJ     (INTER + CONV_DIM + HEADS)     // 8384

// ---------------- scratch ------------------------------------------------
__device__ float g_proj[(size_t)LSEQ * PROJ];
__device__ float g_conv[(size_t)LSEQ * CONV_DIM];
__device__ float g_y[(size_t)LSEQ * INTER];
__device__ float g_dtv[LSEQ * HEADS];
__device__ float g_dA[LSEQ * HEADS];

// ---------------- tf32 helpers --------------------------------------------
__device__ __forceinline__ uint32_t f2tf32(float f) {
    uint32_t i = __float_as_uint(f), o;
    asm("cvt.rn.tf32.f32 %0, %1;" : "=r"(o) : "r"(i));
    return o;
}
__device__ __forceinline__ uint4 f4tf32(float4 v) {
    uint4 o;
    o.x = f2tf32(v.x); o.y = f2tf32(v.y); o.z = f2tf32(v.z); o.w = f2tf32(v.w);
    return o;
}
__device__ __forceinline__ void mma_tf32(float* d, const uint32_t* a, const uint32_t* b) {
    asm volatile(
        "mma.sync.aligned.m16n8k8.row.col.f32.tf32.tf32.f32 "
        "{%0,%1,%2,%3}, {%4,%5,%6,%7}, {%8,%9}, {%0,%1,%2,%3};"
        : "+f"(d[0]), "+f"(d[1]), "+f"(d[2]), "+f"(d[3])
        : "r"(a[0]), "r"(a[1]), "r"(a[2]), "r"(a[3]), "r"(b[0]), "r"(b[1]));
}

// ---------------- tf32 mma.sync GEMM: C[M,N] = A[M,K] * B[N,K]^T -----------
// 128x128x16 CTA tile, 8 warps (2 x 4), 64x32 warp tile, double buffered.
#define BM 128
#define BN 128
#define BK 16
#define SSTR 20   // smem row stride in words (BK + 4 pad)

__global__ __launch_bounds__(256) void gemm_tf32(const float* __restrict__ A,
                                                 const float* __restrict__ B,
                                                 float* __restrict__ C,
                                                 int M, int N, int K)
{
    __shared__ uint32_t As[2][BM][SSTR];
    __shared__ uint32_t Bs[2][BN][SSTR];

    const int tid  = threadIdx.x;
    const int wid  = tid >> 5;
    const int lane = tid & 31;
    const int wm   = wid & 1;          // 0..1 -> 64-row slab
    const int wn   = wid >> 1;         // 0..3 -> 32-col slab
    const int m0   = blockIdx.y * BM;
    const int n0   = blockIdx.x * BN;
    const int lg   = lane >> 2;        // groupID 0..7
    const int lc   = lane & 3;         // threadID-in-group 0..3

    float acc[4][4][4];
#pragma unroll
    for (int i = 0; i < 4; ++i)
#pragma unroll
        for (int j = 0; j < 4; ++j)
#pragma unroll
            for (int q = 0; q < 4; ++q) acc[i][j][q] = 0.f;

    const int nst = K / BK;

    // stage-0 load
    {
#pragma unroll
        for (int it = 0; it < 2; ++it) {
            int f = tid + it * 256;    // 0..511 float4 slots
            int r = f >> 2, kq = f & 3;
            {
                float4 v = *reinterpret_cast<const float4*>(&A[(size_t)(m0 + r) * K + kq * 4]);
                *reinterpret_cast<uint4*>(&As[0][r][kq * 4]) = f4tf32(v);
            }
            {
                uint4 u = make_uint4(0u, 0u, 0u, 0u);
                int gn = n0 + r;
                if (gn < N) {
                    float4 v = *reinterpret_cast<const float4*>(&B[(size_t)gn * K + kq * 4]);
                    u = f4tf32(v);
                }
                *reinterpret_cast<uint4*>(&Bs[0][r][kq * 4]) = u;
            }
        }
    }
    __syncthreads();

    for (int s = 0; s < nst; ++s) {
        const int buf  = s & 1;
        const bool more = (s + 1 < nst);

        uint4 pa[2], pb[2];
        if (more) {
            const int k0 = (s + 1) * BK;
#pragma unroll
            for (int it = 0; it < 2; ++it) {
                int f = tid + it * 256;
                int r = f >> 2, kq = f & 3;
                float4 va = *reinterpret_cast<const float4*>(&A[(size_t)(m0 + r) * K + k0 + kq * 4]);
                pa[it] = f4tf32(va);
                uint4 u = make_uint4(0u, 0u, 0u, 0u);
                int gn = n0 + r;
                if (gn < N) {
                    float4 vb = *reinterpret_cast<const float4*>(&B[(size_t)gn * K + k0 + kq * 4]);
                    u = f4tf32(vb);
                }
                pb[it] = u;
            }
        }

#pragma unroll
        for (int ks = 0; ks < BK; ks += 8) {
            uint32_t af[4][4], bf[4][2];
#pragma unroll
            for (int mt = 0; mt < 4; ++mt) {
                int row = wm * 64 + mt * 16 + lg;
                af[mt][0] = As[buf][row][ks + lc];
                af[mt][1] = As[buf][row + 8][ks + lc];
                af[mt][2] = As[buf][row][ks + 4 + lc];
                af[mt][3] = As[buf][row + 8][ks + 4 + lc];
            }
#pragma unroll
            for (int nt = 0; nt < 4; ++nt) {
                int col = wn * 32 + nt * 8 + lg;
                bf[nt][0] = Bs[buf][col][ks + lc];
                bf[nt][1] = Bs[buf][col][ks + 4 + lc];
            }
#pragma unroll
            for (int mt = 0; mt < 4; ++mt)
#pragma unroll
                for (int nt = 0; nt < 4; ++nt)
                    mma_tf32(acc[mt][nt], af[mt], bf[nt]);
        }

        if (more) {
            const int nb = buf ^ 1;
#pragma unroll
            for (int it = 0; it < 2; ++it) {
                int f = tid + it * 256;
                int r = f >> 2, kq = f & 3;
                *reinterpret_cast<uint4*>(&As[nb][r][kq * 4]) = pa[it];
                *reinterpret_cast<uint4*>(&Bs[nb][r][kq * 4]) = pb[it];
            }
            __syncthreads();
        }
    }

    // epilogue
#pragma unroll
    for (int mt = 0; mt < 4; ++mt) {
        int r0 = m0 + wm * 64 + mt * 16 + lg;
#pragma unroll
        for (int nt = 0; nt < 4; ++nt) {
            int gc = n0 + wn * 32 + nt * 8 + lc * 2;
            if (gc < N) {
                *reinterpret_cast<float2*>(&C[(size_t)r0 * N + gc]) =
                    make_float2(acc[mt][nt][0], acc[mt][nt][1]);
                *reinterpret_cast<float2*>(&C[(size_t)(r0 + 8) * N + gc]) =
                    make_float2(acc[mt][nt][2], acc[mt][nt][3]);
            }
        }
    }
}

// ---------------- conv + silu ---------------------------------------------
__global__ void conv_silu_kernel(const float* __restrict__ conv_w,
                                 const float* __restrict__ conv_b)
{
    int idx = blockIdx.x * blockDim.x + threadIdx.x;
    if (idx >= LSEQ * CONV_DIM) return;
    int c = idx % CONV_DIM;
    int t = idx / CONV_DIM;
    const float4 w = *reinterpret_cast<const float4*>(&conv_w[c * 4]);
    const float* col = g_proj + INTER + c;
    float acc = conv_b[c];
    if (t - 3 >= 0) acc = fmaf(col[(size_t)(t - 3) * PROJ], w.x, acc);
    if (t - 2 >= 0) acc = fmaf(col[(size_t)(t - 2) * PROJ], w.y, acc);
    if (t - 1 >= 0) acc = fmaf(col[(size_t)(t - 1) * PROJ], w.z, acc);
    acc = fmaf(col[(size_t)t * PROJ], w.w, acc);
    g_conv[idx] = acc / (1.f + expf(-acc));
}

// ---------------- dt transform ---------------------------------------------
__global__ void dt_kernel(const float* __restrict__ dt_bias,
                          const float* __restrict__ A_log)
{
    int idx = blockIdx.x * blockDim.x + threadIdx.x;
    if (idx >= LSEQ * HEADS) return;
    int h = idx & (HEADS - 1);
    int t = idx >> 6;
    float z = g_proj[(size_t)t * PROJ + INTER + CONV_DIM + h] + dt_bias[h];
    float d = (z > 20.f) ? z : log1pf(expf(z));
    float A = -expf(A_log[h]);
    g_dtv[idx] = d;
    g_dA[idx]  = expf(d * A);
}

// ---------------- selective scan: chunked + double-buffered -----------------
#define TCH 8
#define NCH (LSEQ / TCH)
__global__ __launch_bounds__(256) void scan_kernel(const float* __restrict__ D)
{
    const int h     = blockIdx.x >> 1;
    const int phalf = blockIdx.x & 1;
    const int tid   = threadIdx.x;
    const int pl    = tid >> 3;           // 0..31
    const int pg    = phalf * 32 + pl;
    const int n0    = (tid & 7) * 8;
    const float Dh  = D[h];

    __shared__ float sBC[2][TCH][128];    // [k][0..63]=B, [64..127]=C
    __shared__ float sX[2][TCH][32];
    __shared__ float sDT[2][TCH], sDA[2][TCH];

    const int lrow = tid >> 5;            // 0..7 timestep in chunk
    const int lcol = tid & 31;

    {
        const float* rowp = g_conv + (size_t)lrow * CONV_DIM;
        *reinterpret_cast<float4*>(&sBC[0][lrow][lcol * 4]) =
            *reinterpret_cast<const float4*>(&rowp[INTER + lcol * 4]);
        sX[0][lrow][lcol] = rowp[h * HEAD_DIM + phalf * 32 + lcol];
        if (tid < TCH)            sDT[0][tid]       = g_dtv[tid * HEADS + h];
        else if (tid < 2 * TCH)   sDA[0][tid - TCH] = g_dA[(tid - TCH) * HEADS + h];
    }
    __syncthreads();

    float s[8];
#pragma unroll
    for (int i = 0; i < 8; ++i) s[i] = 0.f;

    for (int c = 0; c < NCH; ++c) {
        const int buf = c & 1;
        const int t0  = c * TCH;

        float4 nBC; float nX = 0.f, nS = 0.f;
        const bool more = (c + 1 < NCH);
        if (more) {
            int t = t0 + TCH + lrow;
            const float* rowp = g_conv + (size_t)t * CONV_DIM;
            nBC = *reinterpret_cast<const float4*>(&rowp[INTER + lcol * 4]);
            nX  = rowp[h * HEAD_DIM + phalf * 32 + lcol];
            if (tid < TCH)           nS = g_dtv[(t0 + TCH + tid) * HEADS + h];
            else if (tid < 2 * TCH)  nS = g_dA[(t0 + TCH + tid - TCH) * HEADS + h];
        }

#pragma unroll
        for (int k = 0; k < TCH; ++k) {
            const float a   = sDA[buf][k];
            const float dtv = sDT[buf][k];
            const float xv  = sX[buf][k][pl];
            const float dtx = dtv * xv;
            float4 b0 = *reinterpret_cast<const float4*>(&sBC[buf][k][n0]);
            float4 b1 = *reinterpret_cast<const float4*>(&sBC[buf][k][n0 + 4]);
            float4 c0 = *reinterpret_cast<const float4*>(&sBC[buf][k][64 + n0]);
            float4 c1 = *reinterpret_cast<const float4*>(&sBC[buf][k][64 + n0 + 4]);
            float accv;
            s[0] = fmaf(a, s[0], dtx * b0.x); accv = s[0] * c0.x;
            s[1] = fmaf(a, s[1], dtx * b0.y); accv = fmaf(s[1], c0.y, accv);
            s[2] = fmaf(a, s[2], dtx * b0.z); accv = fmaf(s[2], c0.z, accv);
            s[3] = fmaf(a, s[3], dtx * b0.w); accv = fmaf(s[3], c0.w, accv);
            s[4] = fmaf(a, s[4], dtx * b1.x); accv = fmaf(s[4], c1.x, accv);
            s[5] = fmaf(a, s[5], dtx * b1.y); accv = fmaf(s[5], c1.y, accv);
            s[6] = fmaf(a, s[6], dtx * b1.z); accv = fmaf(s[6], c1.z, accv);
            s[7] = fmaf(a, s[7], dtx * b1.w); accv = fmaf(s[7], c1.w, accv);
            accv += __shfl_xor_sync(0xffffffffu, accv, 4);
            accv += __shfl_xor_sync(0xffffffffu, accv, 2);
            accv += __shfl_xor_sync(0xffffffffu, accv, 1);
            if ((tid & 7) == 0)
                g_y[(size_t)(t0 + k) * INTER + h * HEAD_DIM + pg] = accv + Dh * xv;
        }

        if (more) {
            const int nb = buf ^ 1;
            *reinterpret_cast<float4*>(&sBC[nb][lrow][lcol * 4]) = nBC;
            sX[nb][lrow][lcol] = nX;
            if (tid < TCH)           sDT[nb][tid]       = nS;
            else if (tid < 2 * TCH)  sDA[nb][tid - TCH] = nS;
        }
        __syncthreads();
    }
}

// ---------------- RMSNorm * silu(gate) --------------------------------------
__global__ __launch_bounds__(256) void norm_gate_kernel(const float* __restrict__ nw)
{
    const int t = blockIdx.x;
    float* yr = g_y + (size_t)t * INTER;
    __shared__ float red[256];
    float ss = 0.f;
    for (int c = threadIdx.x; c < INTER; c += 256) {
        float v = yr[c];
        ss = fmaf(v, v, ss);
    }
    red[threadIdx.x] = ss;
    __syncthreads();
    for (int off = 128; off > 0; off >>= 1) {
        if (threadIdx.x < off) red[threadIdx.x] += red[threadIdx.x + off];
        __syncthreads();
    }
    const float r = rsqrtf(red[0] / (float)INTER + 1e-6f);
    for (int c = threadIdx.x; c < INTER; c += 256) {
        float g  = g_proj[(size_t)t * PROJ + c];
        float sg = g / (1.f + expf(-g));
        yr[c] = yr[c] * r * nw[c] * sg;
    }
}

// ---------------- launch ------------------------------------------------------
extern "C" void kernel_launch(void* const* d_in, const int* in_sizes, int n_in,
                              void* d_out, int out_size)
{
    const float* hidden     = (const float*)d_in[0];
    const float* in_proj_w  = (const float*)d_in[1];
    const float* conv_w     = (const float*)d_in[2];
    const float* conv_b     = (const float*)d_in[3];
    const float* dt_bias    = (const float*)d_in[4];
    const float* A_log      = (const float*)d_in[5];
    const float* Dv         = (const float*)d_in[6];
    const float* norm_w     = (const float*)d_in[7];
    const float* out_proj_w = (const float*)d_in[8];
    float* out = (float*)d_out;

    float *p_proj = nullptr, *p_y = nullptr;
    cudaGetSymbolAddress((void**)&p_proj, g_proj);
    cudaGetSymbolAddress((void**)&p_y, g_y);

    // 1) proj = hidden @ in_proj_w^T : M=2048, N=8384, K=2048
    {
        dim3 grid((PROJ + BN - 1) / BN, LSEQ / BM);
        gemm_tf32<<<grid, 256>>>(hidden, in_proj_w, p_proj, LSEQ, PROJ, HIDDEN);
    }
    // 2) conv + silu
    {
        int total = LSEQ * CONV_DIM;
        conv_silu_kernel<<<(total + 255) / 256, 256>>>(conv_w, conv_b);
    }
    // 3) dt
    {
        int total = LSEQ * HEADS;
        dt_kernel<<<(total + 255) / 256, 256>>>(dt_bias, A_log);
    }
    // 4) scan
    scan_kernel<<<HEADS * 2, 256>>>(Dv);
    // 5) norm * gate
    norm_gate_kernel<<<LSEQ, 256>>>(norm_w);
    // 6) out = y @ out_proj_w^T : M=2048, N=2048, K=4096
    {
        dim3 grid(HIDDEN / BN, LSEQ / BM);
        gemm_tf32<<<grid, 256>>>(p_y, out_proj_w, out, LSEQ, HIDDEN, INTER);
    }
}